// round 11
// baseline (speedup 1.0000x reference)
#include <cuda_runtime.h>
#include <cstdint>

#define OUT_HW   7
#define NBINS    49
#define CH       256
#define FH       256
#define FW       256
#define HWSZ     (FH*FW)
#define CHWSZ    (CH*HWSZ)
#define CHALF    128           // channels per block (2 blocks per roi)
#define TILE_MAX 8704          // >= 93*93 worst-case rotated bbox

// Permutation: rois sorted by (batch, spatial tile) for L2 locality.
__device__ unsigned int g_perm[1024];

__global__ void sort_rois_kernel(const float* __restrict__ rois, int n)
{
    __shared__ unsigned int sk[1024];
    const int t = threadIdx.x;

    unsigned int key;
    if (t < n && n <= 1024) {
        const float* r = rois + t * 6;
        const int   b  = (int)__ldg(r + 0);
        const float cx = __ldg(r + 1) * 0.25f;
        const float cy = __ldg(r + 2) * 0.25f;
        int tx = (int)(cx * (1.0f / 32.0f)); tx = min(max(tx, 0), 7);
        int ty = (int)(cy * (1.0f / 32.0f)); ty = min(max(ty, 0), 7);
        const unsigned int k = (unsigned int)(b * 64 + ty * 8 + tx);
        key = (k << 10) | (unsigned int)t;
    } else {
        key = 0xFFFFFFFFu;
    }
    sk[t] = key;
    __syncthreads();

    for (int k = 2; k <= 1024; k <<= 1) {
        for (int j = k >> 1; j > 0; j >>= 1) {
            const int ixj = t ^ j;
            if (ixj > t) {
                const unsigned int a = sk[t];
                const unsigned int c = sk[ixj];
                const bool up = ((t & k) == 0);
                if ((a > c) == up) { sk[t] = c; sk[ixj] = a; }
            }
            __syncthreads();
        }
    }

    if (t < n) {
        g_perm[t] = (n <= 1024) ? (sk[t] & 1023u) : (unsigned int)t;
    }
}

__global__ __launch_bounds__(256, 6)
void rroi_align_kernel(const float* __restrict__ feat,
                       const float* __restrict__ rois,
                       float* __restrict__ out)
{
    __shared__ float tile[TILE_MAX];
    __shared__ float part[196];

    const int n    = (int)g_perm[blockIdx.y];
    const int c0   = blockIdx.x * CHALF;
    const int t    = threadIdx.x;
    const int warp = t >> 5;
    const int lane = t & 31;

    // ---- roi params (all threads, warp-uniform) ----
    const float* r = rois + n * 6;
    const int   b  = (int)__ldg(r + 0);
    const float cx = __ldg(r + 1) * 0.25f;
    const float cy = __ldg(r + 2) * 0.25f;
    const float rw = fmaxf(__ldg(r + 3) * 0.25f, 0.0f);
    const float rh = fmaxf(__ldg(r + 4) * 0.25f, 0.0f);
    const float th = __ldg(r + 5);

    const float cs = cosf(th);
    const float sn = sinf(th);
    const float bh = rh * (1.0f / OUT_HW);
    const float bw = rw * (1.0f / OUT_HW);

    // ---- analytic rotated-bbox (feature px), covers all clamped corners ----
    const float half_x = 0.5f * (rw * fabsf(cs) + rh * fabsf(sn));
    const float half_y = 0.5f * (rh * fabsf(cs) + rw * fabsf(sn));
    int tx_lo = min(max((int)floorf(cx - half_x), 0), FW - 2);
    int tx_hi = min(max((int)floorf(cx + half_x), 0), FW - 2) + 1;
    int ty_lo = min(max((int)floorf(cy - half_y), 0), FH - 2);
    int ty_hi = min(max((int)floorf(cy + half_y), 0), FH - 2) + 1;
    const int Wt = tx_hi - tx_lo + 1;            // <= 93 by construction
    const int Ht = ty_hi - ty_lo + 1;
    const int st = Wt | 1;                       // odd stride vs bank conflicts

    // ---- per-thread sample geometry, precomputed once (t < 196) ----
    float wA = 0.f, wB = 0.f, wC = 0.f, wD = 0.f;
    int   o  = 0;
    if (t < 196) {
        const int bin = t >> 2;
        const int s   = t & 3;
        const int ph  = bin / OUT_HW;
        const int pw  = bin - ph * OUT_HW;
        const float sy = (s >> 1) ? 0.75f : 0.25f;
        const float sx = (s & 1)  ? 0.75f : 0.25f;
        const float yy = bh * ((float)ph + sy) - rh * 0.5f;
        const float xx = bw * ((float)pw + sx) - rw * 0.5f;
        const float x  = xx * cs + yy * sn + cx;
        const float y  = yy * cs - xx * sn + cy;

        const bool valid = (y > -1.0f) && (y < (float)FH) &&
                           (x > -1.0f) && (x < (float)FW);

        const float ycl = fminf(fmaxf(y, 0.0f), (float)(FH - 1));
        const float xcl = fminf(fmaxf(x, 0.0f), (float)(FW - 1));
        const float y0f = fminf(floorf(ycl), (float)(FH - 2));
        const float x0f = fminf(floorf(xcl), (float)(FW - 2));
        const int   y0  = (int)y0f;
        const int   x0  = (int)x0f;
        const float ly  = ycl - y0f;
        const float lx  = xcl - x0f;
        const float hy  = 1.0f - ly;
        const float hx  = 1.0f - lx;
        const float vf  = valid ? 0.25f : 0.0f;  // premult 1/(S*S)

        wA = hy * hx * vf;
        wB = hy * lx * vf;
        wC = ly * hx * vf;
        wD = ly * lx * vf;
        o  = (y0 - ty_lo) * st + (x0 - tx_lo);   // tile-relative, in-range
    }

    const float* fb = feat + (size_t)b * CHWSZ + (size_t)c0 * HWSZ;
    float*       ob = out  + (size_t)n * (CH * NBINS) + (size_t)c0 * NBINS;

    // ---- channel loop: coalesced tile load -> smem gathers -> reduce ----
    for (int c = 0; c < CHALF; ++c) {
        const float* fc = fb + (size_t)c * HWSZ + ty_lo * FW + tx_lo;

        // phase A: dense tile load (warp per row)
        for (int row = warp; row < Ht; row += 8) {
            const float* src = fc + row * FW;
            float* dst = tile + row * st;
            for (int xx2 = lane; xx2 < Wt; xx2 += 32)
                dst[xx2] = __ldg(src + xx2);
        }
        __syncthreads();

        // phase B: bilinear gather from smem (196 threads)
        if (t < 196) {
            part[t] = wA * tile[o]      + wB * tile[o + 1]
                    + wC * tile[o + st] + wD * tile[o + st + 1];
        }
        __syncthreads();

        // phase C: 4-sample reduce + coalesced store (49 threads)
        if (t < NBINS) {
            const int q = t << 2;
            ob[(size_t)c * NBINS + t] = part[q] + part[q + 1] + part[q + 2] + part[q + 3];
        }
        __syncthreads();   // tile reused next channel
    }
}

extern "C" void kernel_launch(void* const* d_in, const int* in_sizes, int n_in,
                              void* d_out, int out_size)
{
    const float* feat = (const float*)d_in[0];
    const float* rois = (const float*)d_in[1];
    float*       out  = (float*)d_out;

    const int nrois = in_sizes[1] / 6;   // 1000

    sort_rois_kernel<<<1, 1024>>>(rois, nrois);

    dim3 grid(CH / CHALF, nrois);        // (2, 1000)
    dim3 block(256);
    rroi_align_kernel<<<grid, block>>>(feat, rois, out);
}

// round 12
// speedup vs baseline: 6.1290x; 6.1290x over previous
#include <cuda_runtime.h>
#include <cstdint>

#define OUT_HW   7
#define NBINS    49            // 7*7
#define NSAMP    4             // 2x2 samples per bin
#define CH       256
#define FH       256
#define FW       256
#define HWSZ     (FH*FW)       // 65536
#define CHWSZ    (CH*HWSZ)
#define CPB      64            // channels per block
#define SLOTS    5             // channel slots (5*49 = 245 <= 256 threads)

// Permutation: rois sorted by (batch, spatial tile) for L2 locality.
__device__ unsigned int g_perm[1024];

__global__ void sort_rois_kernel(const float* __restrict__ rois, int n)
{
    __shared__ unsigned int sk[1024];
    const int t = threadIdx.x;

    unsigned int key;
    if (t < n && n <= 1024) {
        const float* r = rois + t * 6;
        const int   b  = (int)__ldg(r + 0);
        const float cx = __ldg(r + 1) * 0.25f;
        const float cy = __ldg(r + 2) * 0.25f;
        int tx = (int)(cx * (1.0f / 32.0f)); tx = min(max(tx, 0), 7);
        int ty = (int)(cy * (1.0f / 32.0f)); ty = min(max(ty, 0), 7);
        const unsigned int k = (unsigned int)(b * 64 + ty * 8 + tx);
        key = (k << 10) | (unsigned int)t;
    } else {
        key = 0xFFFFFFFFu;
    }
    sk[t] = key;
    __syncthreads();

    for (int k = 2; k <= 1024; k <<= 1) {
        for (int j = k >> 1; j > 0; j >>= 1) {
            const int ixj = t ^ j;
            if (ixj > t) {
                const unsigned int a = sk[t];
                const unsigned int c = sk[ixj];
                const bool up = ((t & k) == 0);
                if ((a > c) == up) { sk[t] = c; sk[ixj] = a; }
            }
            __syncthreads();
        }
    }

    if (t < n) {
        g_perm[t] = (n <= 1024) ? (sk[t] & 1023u) : (unsigned int)t;
    }
}

__global__ __launch_bounds__(256, 4)
void rroi_align_kernel(const float* __restrict__ feat,
                       const float* __restrict__ rois,
                       float* __restrict__ out)
{
    const int n     = (int)g_perm[blockIdx.y];   // sorted roi order
    const int c0    = blockIdx.x * CPB;
    const int t     = threadIdx.x;
    const int cslot = t / NBINS;
    const int bin   = t - cslot * NBINS;

    // ---- per-roi parameters (broadcast loads) ----
    const float* r = rois + n * 6;
    const int   b  = (int)__ldg(r + 0);
    const float cx = __ldg(r + 1) * 0.25f;
    const float cy = __ldg(r + 2) * 0.25f;
    const float rw = fmaxf(__ldg(r + 3) * 0.25f, 0.0f);
    const float rh = fmaxf(__ldg(r + 4) * 0.25f, 0.0f);
    const float th = __ldg(r + 5);

    const float cs = cosf(th);
    const float sn = sinf(th);
    const float bh = rh * (1.0f / OUT_HW);
    const float bw = rw * (1.0f / OUT_HW);

    const int ph = bin / OUT_HW;
    const int pw = bin - ph * OUT_HW;

    // ---- precompute 4 samples: aligned base offsets + weights ----
    float w00[NSAMP], w01[NSAMP], w10[NSAMP], w11[NSAMP];
    int   offa[NSAMP];
    int   kpack = 0;
#pragma unroll
    for (int s = 0; s < NSAMP; ++s) {
        const float sy = (s >> 1) ? 0.75f : 0.25f;
        const float sx = (s & 1)  ? 0.75f : 0.25f;
        const float yy = bh * ((float)ph + sy) - rh * 0.5f;
        const float xx = bw * ((float)pw + sx) - rw * 0.5f;
        const float x  = xx * cs + yy * sn + cx;
        const float y  = yy * cs - xx * sn + cy;

        const bool valid = (y > -1.0f) && (y < (float)FH) &&
                           (x > -1.0f) && (x < (float)FW);

        const float ycl = fminf(fmaxf(y, 0.0f), (float)(FH - 1));
        const float xcl = fminf(fmaxf(x, 0.0f), (float)(FW - 1));
        const float y0f = fminf(floorf(ycl), (float)(FH - 2));
        const float x0f = fminf(floorf(xcl), (float)(FW - 2));
        const int   y0  = (int)y0f;
        const int   x0  = (int)x0f;
        const float ly  = ycl - y0f;
        const float lx  = xcl - x0f;
        const float hy  = 1.0f - ly;
        const float hx  = 1.0f - lx;
        const float vf  = valid ? 0.25f : 0.0f;   // premult 1/(S*S)

        w00[s] = hy * hx * vf;
        w01[s] = hy * lx * vf;
        w10[s] = ly * hx * vf;
        w11[s] = ly * lx * vf;
        offa[s] = y0 * FW + (x0 & ~3);            // 16B-aligned base
        kpack  |= (x0 & 3) << (2 * s);            // lane within float4
    }

    if (cslot >= SLOTS) return;  // tail threads only helped warp-uniform math

    const float* fb = feat + (size_t)b * CHWSZ;
    float*       ob = out  + (size_t)n * (CH * NBINS) + bin;

    // ---- channel mainloop: 8 x LDG.128 + predicated scalar top-ups ----
#pragma unroll 1
    for (int c = c0 + cslot; c < c0 + CPB; c += SLOTS) {
        const float* fc = fb + (size_t)c * HWSZ;

        float4 r0[NSAMP], r1[NSAMP];
        float  e0[NSAMP], e1[NSAMP];
#pragma unroll
        for (int s = 0; s < NSAMP; ++s) {
            const float* p = fc + offa[s];
            r0[s] = __ldg((const float4*)p);
            r1[s] = __ldg((const float4*)(p + FW));
            const int k = (kpack >> (2 * s)) & 3;
            e0[s] = 0.0f; e1[s] = 0.0f;
            if (k == 3) {                         // x0&3==3 -> x1 in next quad
                e0[s] = __ldg(p + 4);             // x0<=251 here, in-bounds
                e1[s] = __ldg(p + FW + 4);
            }
        }

        float acc = 0.0f;
#pragma unroll
        for (int s = 0; s < NSAMP; ++s) {
            const int k = (kpack >> (2 * s)) & 3;
            const float v00 = (k == 0) ? r0[s].x : (k == 1) ? r0[s].y
                            : (k == 2) ? r0[s].z : r0[s].w;
            const float v01 = (k == 0) ? r0[s].y : (k == 1) ? r0[s].z
                            : (k == 2) ? r0[s].w : e0[s];
            const float v10 = (k == 0) ? r1[s].x : (k == 1) ? r1[s].y
                            : (k == 2) ? r1[s].z : r1[s].w;
            const float v11 = (k == 0) ? r1[s].y : (k == 1) ? r1[s].z
                            : (k == 2) ? r1[s].w : e1[s];
            acc += w00[s] * v00 + w01[s] * v01 + w10[s] * v10 + w11[s] * v11;
        }
        ob[(size_t)c * NBINS] = acc;
    }
}

extern "C" void kernel_launch(void* const* d_in, const int* in_sizes, int n_in,
                              void* d_out, int out_size)
{
    const float* feat = (const float*)d_in[0];
    const float* rois = (const float*)d_in[1];
    float*       out  = (float*)d_out;

    const int nrois = in_sizes[1] / 6;   // 1000

    sort_rois_kernel<<<1, 1024>>>(rois, nrois);

    dim3 grid(CH / CPB, nrois);          // (4, 1000)
    dim3 block(256);
    rroi_align_kernel<<<grid, block>>>(feat, rois, out);
}

// round 13
// speedup vs baseline: 6.9738x; 1.1378x over previous
#include <cuda_runtime.h>
#include <cstdint>

#define OUT_HW   7
#define NBINS    49            // 7*7
#define NSAMP    4             // 2x2 samples per bin
#define CH       256
#define FH       256
#define FW       256
#define HWSZ     (FH*FW)       // 65536
#define CHWSZ    (CH*HWSZ)
#define CPB      64            // channels per block
#define NSLOT    4             // channel slots (t>>6), warp-uniform

// Permutation: rois sorted by (batch, spatial tile) for L2 locality.
__device__ unsigned int g_perm[1024];

__global__ void sort_rois_kernel(const float* __restrict__ rois, int n)
{
    __shared__ unsigned int sk[1024];
    const int t = threadIdx.x;

    unsigned int key;
    if (t < n && n <= 1024) {
        const float* r = rois + t * 6;
        const int   b  = (int)__ldg(r + 0);
        const float cx = __ldg(r + 1) * 0.25f;
        const float cy = __ldg(r + 2) * 0.25f;
        int tx = (int)(cx * (1.0f / 32.0f)); tx = min(max(tx, 0), 7);
        int ty = (int)(cy * (1.0f / 32.0f)); ty = min(max(ty, 0), 7);
        const unsigned int k = (unsigned int)(b * 64 + ty * 8 + tx);
        key = (k << 10) | (unsigned int)t;
    } else {
        key = 0xFFFFFFFFu;
    }
    sk[t] = key;
    __syncthreads();

    for (int k = 2; k <= 1024; k <<= 1) {
        for (int j = k >> 1; j > 0; j >>= 1) {
            const int ixj = t ^ j;
            if (ixj > t) {
                const unsigned int a = sk[t];
                const unsigned int c = sk[ixj];
                const bool up = ((t & k) == 0);
                if ((a > c) == up) { sk[t] = c; sk[ixj] = a; }
            }
            __syncthreads();
        }
    }

    if (t < n) {
        g_perm[t] = (n <= 1024) ? (sk[t] & 1023u) : (unsigned int)t;
    }
}

__global__ __launch_bounds__(256, 5)
void rroi_align_kernel(const float* __restrict__ feat,
                       const float* __restrict__ rois,
                       float* __restrict__ out)
{
    const int n     = (int)g_perm[blockIdx.y];   // sorted roi order
    const int c0    = blockIdx.x * CPB;
    const int t     = threadIdx.x;
    const int cslot = t >> 6;                    // warp-uniform channel slot
    const int bslot = t & 63;
    const bool wr   = (bslot < NBINS);           // lanes 49-63 are shadows
    const int bin   = wr ? bslot : (NBINS - 1);  // shadow lanes copy bin 48
                                                 // (same addr -> free dedup)

    // ---- per-roi parameters (broadcast loads) ----
    const float* r = rois + n * 6;
    const int   b  = (int)__ldg(r + 0);
    const float cx = __ldg(r + 1) * 0.25f;
    const float cy = __ldg(r + 2) * 0.25f;
    const float rw = fmaxf(__ldg(r + 3) * 0.25f, 0.0f);
    const float rh = fmaxf(__ldg(r + 4) * 0.25f, 0.0f);
    const float th = __ldg(r + 5);

    const float cs = cosf(th);
    const float sn = sinf(th);
    const float bh = rh * (1.0f / OUT_HW);
    const float bw = rw * (1.0f / OUT_HW);

    const int ph = bin / OUT_HW;
    const int pw = bin - ph * OUT_HW;

    // ---- precompute 4 samples: gather offset + premultiplied weights ----
    float w00[NSAMP], w01[NSAMP], w10[NSAMP], w11[NSAMP];
    int   off[NSAMP];
#pragma unroll
    for (int s = 0; s < NSAMP; ++s) {
        const float sy = (s >> 1) ? 0.75f : 0.25f;
        const float sx = (s & 1)  ? 0.75f : 0.25f;
        const float yy = bh * ((float)ph + sy) - rh * 0.5f;
        const float xx = bw * ((float)pw + sx) - rw * 0.5f;
        const float x  = xx * cs + yy * sn + cx;
        const float y  = yy * cs - xx * sn + cy;

        const bool valid = (y > -1.0f) && (y < (float)FH) &&
                           (x > -1.0f) && (x < (float)FW);

        const float ycl = fminf(fmaxf(y, 0.0f), (float)(FH - 1));
        const float xcl = fminf(fmaxf(x, 0.0f), (float)(FW - 1));
        const float y0f = fminf(floorf(ycl), (float)(FH - 2));
        const float x0f = fminf(floorf(xcl), (float)(FW - 2));
        const int   y0  = (int)y0f;
        const int   x0  = (int)x0f;
        const float ly  = ycl - y0f;
        const float lx  = xcl - x0f;
        const float hy  = 1.0f - ly;
        const float hx  = 1.0f - lx;
        const float vf  = valid ? 0.25f : 0.0f;   // premultiply 1/(S*S)

        w00[s] = hy * hx * vf;
        w01[s] = hy * lx * vf;
        w10[s] = ly * hx * vf;
        w11[s] = ly * lx * vf;
        off[s] = y0 * FW + x0;
    }

    const float* fb = feat + (size_t)b * CHWSZ;
    float*       ob = out  + (size_t)n * (CH * NBINS) + bin;

    // ---- channel mainloop: 2 channels per iteration for 32-deep MLP ----
    // each thread: channels c0+cslot, step NSLOT -> 16 channels (8 iters)
#pragma unroll 1
    for (int c = c0 + cslot; c < c0 + CPB; c += 2 * NSLOT) {
        const float* fcA = fb + (size_t)c * HWSZ;
        const float* fcB = fcA + (size_t)NSLOT * HWSZ;
        float accA = 0.0f, accB = 0.0f;

        float a00[NSAMP], a01[NSAMP], a10[NSAMP], a11[NSAMP];
        float b00[NSAMP], b01[NSAMP], b10[NSAMP], b11[NSAMP];
#pragma unroll
        for (int s = 0; s < NSAMP; ++s) {
            const float* pA = fcA + off[s];
            const float* pB = fcB + off[s];
            a00[s] = __ldg(pA);
            a01[s] = __ldg(pA + 1);
            a10[s] = __ldg(pA + FW);
            a11[s] = __ldg(pA + FW + 1);
            b00[s] = __ldg(pB);
            b01[s] = __ldg(pB + 1);
            b10[s] = __ldg(pB + FW);
            b11[s] = __ldg(pB + FW + 1);
        }
#pragma unroll
        for (int s = 0; s < NSAMP; ++s) {
            accA += w00[s] * a00[s] + w01[s] * a01[s] + w10[s] * a10[s] + w11[s] * a11[s];
            accB += w00[s] * b00[s] + w01[s] * b01[s] + w10[s] * b10[s] + w11[s] * b11[s];
        }
        if (wr) {
            ob[(size_t)c * NBINS] = accA;
            ob[(size_t)(c + NSLOT) * NBINS] = accB;
        }
    }
}

extern "C" void kernel_launch(void* const* d_in, const int* in_sizes, int n_in,
                              void* d_out, int out_size)
{
    const float* feat = (const float*)d_in[0];
    const float* rois = (const float*)d_in[1];
    float*       out  = (float*)d_out;

    const int nrois = in_sizes[1] / 6;   // 1000

    sort_rois_kernel<<<1, 1024>>>(rois, nrois);

    dim3 grid(CH / CPB, nrois);          // (4, 1000)
    dim3 block(256);
    rroi_align_kernel<<<grid, block>>>(feat, rois, out);
}